// round 2
// baseline (speedup 1.0000x reference)
#include <cuda_runtime.h>
#include <math.h>

#define Bk 8
#define Nn 8192
#define Ee 16384
#define Dd 128
#define Mm 20
#define Ll 3

#define EPB 64
#define ETHREADS 512
#define SMEM_EDGE ((5*EPB*Dd + 16*Dd)*4)

// -------- scratch (device globals; no allocation allowed) --------
__device__ float g_h[(size_t)Bk*Nn*Dd];      // node state (33.5 MB)
__device__ float g_de[(size_t)Bk*Nn*Dd];     // dist_emb  (33.5 MB)
__device__ float g_aggr[(size_t)Bk*Nn*Dd];   // scatter target (33.5 MB)
__device__ float g_scores[Bk*Nn];

// ---------------- prep: dist_emb + h init ----------------
__global__ void prep_kernel(const int* __restrict__ dists,
                            const float* __restrict__ noise,
                            const float* __restrict__ dtab)
{
    int i = blockIdx.x * blockDim.x + threadIdx.x;   // over B*N*D/4
    if (i >= Bk*Nn*Dd/4) return;
    int node = i >> 5;          // D/4 = 32
    int c = i & 31;
    int di = dists[node];
    di = di < 0 ? 0 : (di > 9 ? 9 : di);
    float4 dv = __ldg(((const float4*)(dtab + (size_t)di*Dd)) + c);
    float4 nz = ((const float4*)noise)[i];
    float4 h;
    h.x = dv.x + 0.1f*nz.x; h.y = dv.y + 0.1f*nz.y;
    h.z = dv.z + 0.1f*nz.z; h.w = dv.w + 0.1f*nz.w;
    ((float4*)g_de)[i] = dv;
    ((float4*)g_h)[i]  = h;
}

// ---------------- edge message GEMM + fused scatter-add ----------------
// block: 64 edges x 128 outputs, 512 threads, K=640 in 5 segments of 128.
__global__ void __launch_bounds__(512)
edge_msg_kernel(const int* __restrict__ edge_index,
                const int* __restrict__ rels,
                const int* __restrict__ edge_mask,      // int32 bool
                const float* __restrict__ conf,
                const float* __restrict__ rel_table,
                const float* __restrict__ W,      // (640,128) for this layer
                const float* __restrict__ bias)   // (128,)
{
    extern __shared__ float sm[];
    float* s_comp = sm;
    float* s_hs = s_comp + EPB*Dd;
    float* s_ds = s_hs   + EPB*Dd;
    float* s_hr = s_ds   + EPB*Dd;
    float* s_cf = s_hr   + EPB*Dd;
    float* s_w  = s_cf   + EPB*Dd;   // 16 x 128
    __shared__ int   s_src[EPB], s_tgt[EPB], s_rel[EPB];
    __shared__ float s_em[EPB];

    int blk = blockIdx.x;
    int b  = blk >> 8;               // E/EPB = 256
    int e0 = (blk & 255) * EPB;
    int t  = threadIdx.x;

    if (t < EPB) {
        int e = e0 + t;
        s_src[t] = edge_index[(size_t)b*2*Ee + e];
        s_tgt[t] = edge_index[(size_t)b*2*Ee + Ee + e];
        s_rel[t] = rels[(size_t)b*Ee + e];
        s_em[t]  = edge_mask[(size_t)b*Ee + e] ? 1.f : 0.f;
    }
    __syncthreads();

    // gather operand tiles (rows are contiguous 512B -> coalesced float4)
    for (int i = t; i < EPB*(Dd/4); i += ETHREADS) {
        int e = i >> 5;
        int c = i & 31;
        int ge = e0 + e;
        size_t nb = ((size_t)b*Nn + s_src[e]) * Dd;
        ((float4*)s_hs)[i] = __ldg(((const float4*)(g_h  + nb)) + c);
        ((float4*)s_ds)[i] = __ldg(((const float4*)(g_de + nb)) + c);
        ((float4*)s_hr)[i] = __ldg(((const float4*)(rel_table + (size_t)s_rel[e]*Dd)) + c);
        ((float4*)s_cf)[i] = __ldg(((const float4*)(conf + ((size_t)b*Ee + ge)*Dd)) + c);
    }
    __syncthreads();
    for (int i = t; i < EPB*Dd; i += ETHREADS) s_comp[i] = s_hs[i]*s_hr[i];
    __syncthreads();

    int tx = t & 31;     // 4 output cols: tx*4..tx*4+3
    int ty = t >> 5;     // edges {ty, ty+16, ty+32, ty+48}
    float acc[4][4];
    #pragma unroll
    for (int i = 0; i < 4; i++) { acc[i][0]=0.f; acc[i][1]=0.f; acc[i][2]=0.f; acc[i][3]=0.f; }

    const float* tiles[5] = {s_comp, s_hs, s_ds, s_hr, s_cf};

    for (int seg = 0; seg < 5; seg++) {
        const float* A = tiles[seg];
        for (int kc = 0; kc < Dd; kc += 16) {
            {   // load W tile: 512 float4, one per thread
                int kk = t >> 5, c4 = t & 31;
                ((float4*)s_w)[t] = __ldg(((const float4*)(W + (size_t)(seg*Dd + kc + kk)*Dd)) + c4);
            }
            __syncthreads();
            #pragma unroll
            for (int kk = 0; kk < 16; kk++) {
                float4 w = ((const float4*)s_w)[kk*32 + tx];
                #pragma unroll
                for (int es = 0; es < 4; es++) {
                    float a = A[(ty + es*16)*Dd + kc + kk];   // warp-broadcast
                    acc[es][0] = fmaf(a, w.x, acc[es][0]);
                    acc[es][1] = fmaf(a, w.y, acc[es][1]);
                    acc[es][2] = fmaf(a, w.z, acc[es][2]);
                    acc[es][3] = fmaf(a, w.w, acc[es][3]);
                }
            }
            __syncthreads();
        }
    }

    float b0 = bias[tx*4+0], b1 = bias[tx*4+1], b2 = bias[tx*4+2], b3 = bias[tx*4+3];
    #pragma unroll
    for (int es = 0; es < 4; es++) {
        int e = ty + es*16;
        if (s_em[e] != 0.f) {      // masked edges contribute exactly 0 -> skip
            float* dst = g_aggr + ((size_t)b*Nn + s_tgt[e])*Dd + tx*4;
            atomicAdd(dst+0, fmaxf(acc[es][0] + b0, 0.f));
            atomicAdd(dst+1, fmaxf(acc[es][1] + b1, 0.f));
            atomicAdd(dst+2, fmaxf(acc[es][2] + b2, 0.f));
            atomicAdd(dst+3, fmaxf(acc[es][3] + b3, 0.f));
        }
    }
}

// ---------------- node update GEMM: h = aggr @ W + b + h ----------------
__global__ void __launch_bounds__(512)
update_kernel(const float* __restrict__ W, const float* __restrict__ bias)
{
    __shared__ float s_a[EPB*Dd];
    __shared__ float s_w[16*Dd];
    size_t row0 = (size_t)blockIdx.x * EPB;
    int t = threadIdx.x;

    for (int i = t; i < EPB*(Dd/4); i += 512)
        ((float4*)s_a)[i] = ((const float4*)(g_aggr + row0*Dd))[i];
    __syncthreads();

    int tx = t & 31, ty = t >> 5;
    float acc[4][4];
    #pragma unroll
    for (int i = 0; i < 4; i++) { acc[i][0]=0.f; acc[i][1]=0.f; acc[i][2]=0.f; acc[i][3]=0.f; }

    for (int kc = 0; kc < Dd; kc += 16) {
        {
            int kk = t >> 5, c4 = t & 31;
            ((float4*)s_w)[t] = __ldg(((const float4*)(W + (size_t)(kc + kk)*Dd)) + c4);
        }
        __syncthreads();
        #pragma unroll
        for (int kk = 0; kk < 16; kk++) {
            float4 w = ((const float4*)s_w)[kk*32 + tx];
            #pragma unroll
            for (int es = 0; es < 4; es++) {
                float a = s_a[(ty + es*16)*Dd + kc + kk];
                acc[es][0] = fmaf(a, w.x, acc[es][0]);
                acc[es][1] = fmaf(a, w.y, acc[es][1]);
                acc[es][2] = fmaf(a, w.z, acc[es][2]);
                acc[es][3] = fmaf(a, w.w, acc[es][3]);
            }
        }
        __syncthreads();
    }

    float b0 = bias[tx*4+0], b1 = bias[tx*4+1], b2 = bias[tx*4+2], b3 = bias[tx*4+3];
    #pragma unroll
    for (int es = 0; es < 4; es++) {
        size_t row = row0 + ty + es*16;
        float4* hp = ((float4*)(g_h + row*Dd)) + tx;
        float4 hv = *hp;
        hv.x += acc[es][0] + b0;
        hv.y += acc[es][1] + b1;
        hv.z += acc[es][2] + b2;
        hv.w += acc[es][3] + b3;
        *hp = hv;
    }
}

// ---------------- attention scores ----------------
__global__ void score_kernel(const float* __restrict__ attW, const float* __restrict__ attb,
                             const int* __restrict__ node_mask,      // int32 bool
                             const float* __restrict__ rq)
{
    int gw = blockIdx.x*8 + (threadIdx.x >> 5);   // global node in [0, B*N)
    int lane = threadIdx.x & 31;
    int b = gw / Nn, n = gw % Nn;
    const float* hrow = g_h + (size_t)gw*Dd;
    float s = 0.f;
    #pragma unroll
    for (int i = 0; i < 4; i++) {
        int d = lane + i*32;
        s = fmaf(hrow[d], attW[d], s);
        s = fmaf(rq[b*Dd + d], attW[Dd + d], s);
    }
    #pragma unroll
    for (int o = 16; o; o >>= 1) s += __shfl_xor_sync(0xffffffffu, s, o);
    if (lane == 0) {
        s += attb[0];
        s = (s > 0.f) ? s : 0.01f * s;           // leaky_relu(0.01)
        if (!node_mask[(size_t)b*Nn + n]) s = -1e9f;
        g_scores[gw] = s;
    }
}

// ---------------- softmax + top-20 + output gather (1 block / batch) ----------------
__global__ void __launch_bounds__(1024)
topk_kernel(const int* __restrict__ node_mask, float* __restrict__ out)
{
    __shared__ float ss[Nn];          // 32 KB
    __shared__ float rv[1024];
    __shared__ int   ri[1024];
    __shared__ float s_max, s_sum;
    __shared__ int   top_i[Mm];
    __shared__ float top_v[Mm];

    int b = blockIdx.x;
    int t = threadIdx.x;

    for (int i = t; i < Nn; i += 1024) ss[i] = g_scores[(size_t)b*Nn + i];
    __syncthreads();

    // max
    float m = -INFINITY;
    for (int i = t; i < Nn; i += 1024) m = fmaxf(m, ss[i]);
    rv[t] = m; __syncthreads();
    for (int s = 512; s > 0; s >>= 1) { if (t < s) rv[t] = fmaxf(rv[t], rv[t+s]); __syncthreads(); }
    if (t == 0) s_max = rv[0];
    __syncthreads();
    float vmax = s_max;

    // sum exp
    float sum = 0.f;
    for (int i = t; i < Nn; i += 1024) sum += expf(ss[i] - vmax);
    rv[t] = sum; __syncthreads();
    for (int s = 512; s > 0; s >>= 1) { if (t < s) rv[t] += rv[t+s]; __syncthreads(); }
    if (t == 0) s_sum = rv[0];
    __syncthreads();
    float inv = 1.f / s_sum;

    // 20 stable argmax passes (descending, lowest index on tie -> matches lax.top_k)
    for (int sel = 0; sel < Mm; sel++) {
        float bv = -INFINITY; int bi = Nn;
        for (int i = t; i < Nn; i += 1024) {
            float v = ss[i];
            if (v > bv) { bv = v; bi = i; }
        }
        rv[t] = bv; ri[t] = bi; __syncthreads();
        for (int s = 512; s > 0; s >>= 1) {
            if (t < s) {
                if (rv[t+s] > rv[t] || (rv[t+s] == rv[t] && ri[t+s] < ri[t])) {
                    rv[t] = rv[t+s]; ri[t] = ri[t+s];
                }
            }
            __syncthreads();
        }
        if (t == 0) { top_i[sel] = ri[0]; top_v[sel] = rv[0]; ss[ri[0]] = -INFINITY; }
        __syncthreads();
    }

    // H_evd = h[topk] * alpha  (apply node_mask to h for exactness)
    for (int i = t; i < Mm*Dd; i += 1024) {
        int sel = i / Dd, d = i % Dd;
        int idx = top_i[sel];
        float alpha = expf(top_v[sel] - vmax) * inv;
        float mk = node_mask[(size_t)b*Nn + idx] ? 1.f : 0.f;
        float hv = g_h[((size_t)b*Nn + idx)*Dd + d] * mk;
        out[((size_t)b*Mm + sel)*Dd + d] = hv * alpha;
    }
    // t_state = (h * node_mask)[:, 0, :]
    float m0 = node_mask[(size_t)b*Nn] ? 1.f : 0.f;
    for (int d = t; d < Dd; d += 1024)
        out[(size_t)Bk*Mm*Dd + (size_t)b*Dd + d] = g_h[((size_t)b*Nn)*Dd + d] * m0;
}

// ---------------- launch ----------------
extern "C" void kernel_launch(void* const* d_in, const int* in_sizes, int n_in,
                              void* d_out, int out_size)
{
    (void)in_sizes; (void)n_in; (void)out_size;
    const int*   dists      = (const int*)d_in[0];
    const int*   edge_index = (const int*)d_in[1];
    const int*   rels       = (const int*)d_in[2];
    const int*   node_mask  = (const int*)d_in[3];
    const int*   edge_mask  = (const int*)d_in[4];
    const float* rq         = (const float*)d_in[5];
    const float* conf       = (const float*)d_in[6];
    const float* noise      = (const float*)d_in[7];
    const float* dist_table = (const float*)d_in[8];
    const float* rel_table  = (const float*)d_in[9];
    const float* msg_W      = (const float*)d_in[10];
    const float* msg_b      = (const float*)d_in[11];
    const float* upd_W      = (const float*)d_in[12];
    const float* upd_b      = (const float*)d_in[13];
    const float* att_W      = (const float*)d_in[14];
    const float* att_b      = (const float*)d_in[15];
    float* out = (float*)d_out;

    cudaFuncSetAttribute(edge_msg_kernel, cudaFuncAttributeMaxDynamicSharedMemorySize, SMEM_EDGE);
    void* aggr_ptr = nullptr;
    cudaGetSymbolAddress(&aggr_ptr, g_aggr);

    int total4 = Bk*Nn*Dd/4;
    prep_kernel<<<(total4 + 255)/256, 256>>>(dists, noise, dist_table);

    for (int k = 0; k < Ll; k++) {
        cudaMemsetAsync(aggr_ptr, 0, sizeof(float)*(size_t)Bk*Nn*Dd);
        edge_msg_kernel<<<Bk*(Ee/EPB), ETHREADS, SMEM_EDGE>>>(
            edge_index, rels, edge_mask, conf, rel_table,
            msg_W + (size_t)k*5*Dd*Dd, msg_b + (size_t)k*Dd);
        update_kernel<<<Bk*Nn/EPB, 512>>>(upd_W + (size_t)k*Dd*Dd, upd_b + (size_t)k*Dd);
    }

    score_kernel<<<Bk*Nn/8, 256>>>(att_W, att_b, node_mask, rq);
    topk_kernel<<<Bk, 1024>>>(node_mask, out);
}

// round 5
// speedup vs baseline: 3.0341x; 3.0341x over previous
#include <cuda_runtime.h>
#include <cuda_fp16.h>
#include <math.h>
#include <stdint.h>

#define Bk 8
#define Nn 8192
#define Ee 16384
#define Dd 128
#define Mm 20
#define Ll 3

#define STR 72            // smem half stride (conflict-free frags)
#define SM_BYTES ((size_t)(4*128*STR)*2)   // 4 half tiles = 73728 B

// -------- device scratch --------
__device__ float g_h[(size_t)Bk*Nn*Dd];
__device__ float g_de[(size_t)Bk*Nn*Dd];
__device__ float g_aggr[(size_t)Bk*Nn*Dd];
__device__ float g_scores[Bk*Nn];
__device__ __half g_msgWhi[(size_t)Ll*10*128*64];  // [l][chunk][n][k]
__device__ __half g_msgWlo[(size_t)Ll*10*128*64];
__device__ __half g_updWhi[(size_t)Ll*2*128*64];
__device__ __half g_updWlo[(size_t)Ll*2*128*64];

#define MMA_F16(c, a, b0, b1) \
    asm volatile("mma.sync.aligned.m16n8k16.row.col.f32.f16.f16.f32 " \
        "{%0,%1,%2,%3}, {%4,%5,%6,%7}, {%8,%9}, {%0,%1,%2,%3};" \
        : "+f"((c)[0]), "+f"((c)[1]), "+f"((c)[2]), "+f"((c)[3]) \
        : "r"((a)[0]), "r"((a)[1]), "r"((a)[2]), "r"((a)[3]), "r"(b0), "r"(b1))

__device__ __forceinline__ void split2(float x, float y, uint32_t& hi, uint32_t& lo){
    __half hx = __float2half_rn(x), hy = __float2half_rn(y);
    float rx = x - __half2float(hx), ry = y - __half2float(hy);
    __half2 h = __halves2half2(hx, hy);
    __half2 l = __halves2half2(__float2half_rn(rx), __float2half_rn(ry));
    hi = *(uint32_t*)&h; lo = *(uint32_t*)&l;
}

// ---------------- prep: dist_emb + h init ----------------
__global__ void prep_kernel(const int* __restrict__ dists,
                            const float* __restrict__ noise,
                            const float* __restrict__ dtab)
{
    int i = blockIdx.x * blockDim.x + threadIdx.x;
    if (i >= Bk*Nn*Dd/4) return;
    int node = i >> 5;
    int c = i & 31;
    int di = dists[node];
    di = di < 0 ? 0 : (di > 9 ? 9 : di);
    float4 dv = __ldg(((const float4*)(dtab + (size_t)di*Dd)) + c);
    float4 nz = ((const float4*)noise)[i];
    float4 h;
    h.x = dv.x + 0.1f*nz.x; h.y = dv.y + 0.1f*nz.y;
    h.z = dv.z + 0.1f*nz.z; h.w = dv.w + 0.1f*nz.w;
    ((float4*)g_de)[i] = dv;
    ((float4*)g_h)[i]  = h;
}

// ---------------- weight prep: [l][chunk][n][k], fp16 hi/lo split ----------------
__global__ void prep_weights(const float* __restrict__ msgW, const float* __restrict__ updW)
{
    int i = blockIdx.x * blockDim.x + threadIdx.x;
    const int MSGTOT = Ll*5*Dd*Dd;                 // 245760
    if (i < MSGTOT) {
        int l = i / (640*128);
        int k = (i / 128) % 640;
        int n = i & 127;
        int ch = k >> 6, kk = k & 63;
        float w = msgW[i];
        __half hi = __float2half_rn(w);
        __half lo = __float2half_rn(w - __half2float(hi));
        size_t o = (((size_t)(l*10 + ch))*128 + n)*64 + kk;
        g_msgWhi[o] = hi; g_msgWlo[o] = lo;
    } else {
        int j = i - MSGTOT;
        if (j < Ll*Dd*Dd) {
            int l = j / (128*128);
            int k = (j / 128) % 128;
            int n = j & 127;
            int ch = k >> 6, kk = k & 63;
            float w = updW[j];
            __half hi = __float2half_rn(w);
            __half lo = __float2half_rn(w - __half2float(hi));
            size_t o = (((size_t)(l*2 + ch))*128 + n)*64 + kk;
            g_updWhi[o] = hi; g_updWlo[o] = lo;
        }
    }
}

// ---------------- edge message GEMM (fp16-split mma) + fused relu/mask/scatter ----------------
// CTA: 128 edges x 128 outputs, K=640 in 10 chunks of 64. 8 warps: 4(M) x 2(N), warp tile 32x64.
__global__ void __launch_bounds__(256, 2)
edge_hmma_kernel(int layer,
                 const int* __restrict__ edge_index,
                 const int* __restrict__ rels,
                 const int* __restrict__ edge_mask,
                 const float* __restrict__ conf,
                 const float* __restrict__ rel_table,
                 const float* __restrict__ bias)
{
    extern __shared__ __half sm[];
    __half* sAhi = sm;                    // 128 x STR
    __half* sAlo = sAhi + 128*STR;
    __half* sBhi = sAlo + 128*STR;        // 128(n) x STR
    __half* sBlo = sBhi + 128*STR;
    __shared__ int   s_src[128], s_tgt[128], s_rel[128];
    __shared__ float s_em[128], s_bias[128];

    int tid = threadIdx.x, wid = tid >> 5, lane = tid & 31;
    int b  = blockIdx.x >> 7;
    int e0 = (blockIdx.x & 127) << 7;

    if (tid < 128) {
        int e = e0 + tid;
        s_src[tid] = edge_index[(size_t)b*2*Ee + e];
        s_tgt[tid] = edge_index[(size_t)b*2*Ee + Ee + e];
        s_rel[tid] = rels[(size_t)b*Ee + e];
        s_em[tid]  = edge_mask[(size_t)b*Ee + e] ? 1.f : 0.f;
        s_bias[tid] = bias[tid];
    }
    __syncthreads();

    size_t bN = (size_t)b * Nn;
    int wm = wid & 3, wn = wid >> 2;
    int g = lane >> 2, t4 = lane & 3;

    float acc[2][8][4];
    #pragma unroll
    for (int i = 0; i < 2; i++)
        #pragma unroll
        for (int j = 0; j < 8; j++)
            #pragma unroll
            for (int q = 0; q < 4; q++) acc[i][j][q] = 0.f;

    for (int c = 0; c < 10; c++) {
        int seg  = c >> 1;
        int koff = (c & 1) * 64;

        // gather A: 128 edges x 64 floats (2048 float4), fp16 hi/lo split
        #pragma unroll
        for (int it = 0; it < 8; it++) {
            int idx = tid + it*256;
            int e = idx >> 4, q = idx & 15;
            int col = koff + q*4;
            float4 v;
            if (seg == 0) {
                float4 a = *(const float4*)(g_h + (bN + s_src[e])*Dd + col);
                float4 r = *(const float4*)(rel_table + (size_t)s_rel[e]*Dd + col);
                v.x = a.x*r.x; v.y = a.y*r.y; v.z = a.z*r.z; v.w = a.w*r.w;
            } else if (seg == 1) {
                v = *(const float4*)(g_h + (bN + s_src[e])*Dd + col);
            } else if (seg == 2) {
                v = *(const float4*)(g_de + (bN + s_src[e])*Dd + col);
            } else if (seg == 3) {
                v = *(const float4*)(rel_table + (size_t)s_rel[e]*Dd + col);
            } else {
                v = *(const float4*)(conf + ((size_t)b*Ee + e0 + e)*Dd + col);
            }
            uint2 hi2, lo2;
            split2(v.x, v.y, hi2.x, lo2.x);
            split2(v.z, v.w, hi2.y, lo2.y);
            int ho = e*STR + q*4;
            *(uint2*)(sAhi + ho) = hi2;
            *(uint2*)(sAlo + ho) = lo2;
        }
        // B: copy pre-split chunk [n][64]
        {
            const uint4* wh = (const uint4*)(g_msgWhi + ((size_t)(layer*10 + c))*8192);
            const uint4* wl = (const uint4*)(g_msgWlo + ((size_t)(layer*10 + c))*8192);
            #pragma unroll
            for (int it = 0; it < 4; it++) {
                int idx = tid + it*256;
                int n = idx >> 3, q = idx & 7;
                *(uint4*)(sBhi + n*STR + q*8) = __ldg(wh + idx);
                *(uint4*)(sBlo + n*STR + q*8) = __ldg(wl + idx);
            }
        }
        __syncthreads();

        #pragma unroll
        for (int k16 = 0; k16 < 4; k16++) {
            int kb = k16*16;
            uint32_t ahi[2][4], alo[2][4];
            #pragma unroll
            for (int i = 0; i < 2; i++) {
                int r = (wm*32 + i*16 + g)*STR + kb + 2*t4;
                ahi[i][0] = *(uint32_t*)(sAhi + r);
                ahi[i][1] = *(uint32_t*)(sAhi + r + 8*STR);
                ahi[i][2] = *(uint32_t*)(sAhi + r + 8);
                ahi[i][3] = *(uint32_t*)(sAhi + r + 8*STR + 8);
                alo[i][0] = *(uint32_t*)(sAlo + r);
                alo[i][1] = *(uint32_t*)(sAlo + r + 8*STR);
                alo[i][2] = *(uint32_t*)(sAlo + r + 8);
                alo[i][3] = *(uint32_t*)(sAlo + r + 8*STR + 8);
            }
            #pragma unroll
            for (int j = 0; j < 8; j++) {
                int nb = (wn*64 + j*8 + g)*STR + kb + 2*t4;
                uint32_t bh0 = *(uint32_t*)(sBhi + nb), bh1 = *(uint32_t*)(sBhi + nb + 8);
                uint32_t bl0 = *(uint32_t*)(sBlo + nb), bl1 = *(uint32_t*)(sBlo + nb + 8);
                MMA_F16(acc[0][j], ahi[0], bh0, bh1);
                MMA_F16(acc[1][j], ahi[1], bh0, bh1);
                MMA_F16(acc[0][j], ahi[0], bl0, bl1);
                MMA_F16(acc[1][j], ahi[1], bl0, bl1);
                MMA_F16(acc[0][j], alo[0], bh0, bh1);
                MMA_F16(acc[1][j], alo[1], bh0, bh1);
            }
        }
        __syncthreads();
    }

    // epilogue: relu + bias + mask, scatter-add
    #pragma unroll
    for (int i = 0; i < 2; i++) {
        #pragma unroll
        for (int half = 0; half < 2; half++) {
            int row = wm*32 + i*16 + g + half*8;
            if (s_em[row] != 0.f) {
                float* dst = g_aggr + (bN + s_tgt[row])*Dd;
                #pragma unroll
                for (int j = 0; j < 8; j++) {
                    int col = wn*64 + j*8 + t4*2;
                    float v0 = acc[i][j][half*2+0] + s_bias[col];
                    float v1 = acc[i][j][half*2+1] + s_bias[col+1];
                    if (v0 > 0.f) atomicAdd(dst + col,     v0);
                    if (v1 > 0.f) atomicAdd(dst + col + 1, v1);
                }
            }
        }
    }
}

// ---------------- node update GEMM (fp16-split mma): h = aggr @ W + b + h ----------------
__global__ void __launch_bounds__(256, 2)
update_hmma_kernel(int layer, const float* __restrict__ bias)
{
    extern __shared__ __half sm[];
    __half* sAhi = sm;
    __half* sAlo = sAhi + 128*STR;
    __half* sBhi = sAlo + 128*STR;
    __half* sBlo = sBhi + 128*STR;
    __shared__ float s_bias[128];

    int tid = threadIdx.x, wid = tid >> 5, lane = tid & 31;
    size_t r0 = (size_t)blockIdx.x * 128;
    if (tid < 128) s_bias[tid] = bias[tid];
    __syncthreads();

    int wm = wid & 3, wn = wid >> 2;
    int g = lane >> 2, t4 = lane & 3;

    float acc[2][8][4];
    #pragma unroll
    for (int i = 0; i < 2; i++)
        #pragma unroll
        for (int j = 0; j < 8; j++)
            #pragma unroll
            for (int q = 0; q < 4; q++) acc[i][j][q] = 0.f;

    for (int c = 0; c < 2; c++) {
        int koff = c*64;
        #pragma unroll
        for (int it = 0; it < 8; it++) {
            int idx = tid + it*256;
            int row = idx >> 4, q = idx & 15;
            float4 v = *(const float4*)(g_aggr + (r0 + row)*Dd + koff + q*4);
            uint2 hi2, lo2;
            split2(v.x, v.y, hi2.x, lo2.x);
            split2(v.z, v.w, hi2.y, lo2.y);
            int ho = row*STR + q*4;
            *(uint2*)(sAhi + ho) = hi2;
            *(uint2*)(sAlo + ho) = lo2;
        }
        {
            const uint4* wh = (const uint4*)(g_updWhi + ((size_t)(layer*2 + c))*8192);
            const uint4* wl = (const uint4*)(g_updWlo + ((size_t)(layer*2 + c))*8192);
            #pragma unroll
            for (int it = 0; it < 4; it++) {
                int idx = tid + it*256;
                int n = idx >> 3, q = idx & 7;
                *(uint4*)(sBhi + n*STR + q*8) = __ldg(wh + idx);
                *(uint4*)(sBlo + n*STR + q*8) = __ldg(wl + idx);
            }
        }
        __syncthreads();

        #pragma unroll
        for (int k16 = 0; k16 < 4; k16++) {
            int kb = k16*16;
            uint32_t ahi[2][4], alo[2][4];
            #pragma unroll
            for (int i = 0; i < 2; i++) {
                int r = (wm*32 + i*16 + g)*STR + kb + 2*t4;
                ahi[i][0] = *(uint32_t*)(sAhi + r);
                ahi[i][1] = *(uint32_t*)(sAhi + r + 8*STR);
                ahi[i][2] = *(uint32_t*)(sAhi + r + 8);
                ahi[i][3] = *(uint32_t*)(sAhi + r + 8*STR + 8);
                alo[i][0] = *(uint32_t*)(sAlo + r);
                alo[i][1] = *(uint32_t*)(sAlo + r + 8*STR);
                alo[i][2] = *(uint32_t*)(sAlo + r + 8);
                alo[i][3] = *(uint32_t*)(sAlo + r + 8*STR + 8);
            }
            #pragma unroll
            for (int j = 0; j < 8; j++) {
                int nb = (wn*64 + j*8 + g)*STR + kb + 2*t4;
                uint32_t bh0 = *(uint32_t*)(sBhi + nb), bh1 = *(uint32_t*)(sBhi + nb + 8);
                uint32_t bl0 = *(uint32_t*)(sBlo + nb), bl1 = *(uint32_t*)(sBlo + nb + 8);
                MMA_F16(acc[0][j], ahi[0], bh0, bh1);
                MMA_F16(acc[1][j], ahi[1], bh0, bh1);
                MMA_F16(acc[0][j], ahi[0], bl0, bl1);
                MMA_F16(acc[1][j], ahi[1], bl0, bl1);
                MMA_F16(acc[0][j], alo[0], bh0, bh1);
                MMA_F16(acc[1][j], alo[1], bh0, bh1);
            }
        }
        __syncthreads();
    }

    // epilogue: h += d + bias
    #pragma unroll
    for (int i = 0; i < 2; i++) {
        #pragma unroll
        for (int half = 0; half < 2; half++) {
            int row = wm*32 + i*16 + g + half*8;
            float* hp = g_h + (r0 + row)*Dd;
            #pragma unroll
            for (int j = 0; j < 8; j++) {
                int col = wn*64 + j*8 + t4*2;
                hp[col]     += acc[i][j][half*2+0] + s_bias[col];
                hp[col + 1] += acc[i][j][half*2+1] + s_bias[col+1];
            }
        }
    }
}

// ---------------- attention scores ----------------
__global__ void score_kernel(const float* __restrict__ attW, const float* __restrict__ attb,
                             const int* __restrict__ node_mask,
                             const float* __restrict__ rq)
{
    int gw = blockIdx.x*8 + (threadIdx.x >> 5);
    int lane = threadIdx.x & 31;
    int b = gw / Nn, n = gw % Nn;
    const float* hrow = g_h + (size_t)gw*Dd;
    float s = 0.f;
    #pragma unroll
    for (int i = 0; i < 4; i++) {
        int d = lane + i*32;
        s = fmaf(hrow[d], attW[d], s);
        s = fmaf(rq[b*Dd + d], attW[Dd + d], s);
    }
    #pragma unroll
    for (int o = 16; o; o >>= 1) s += __shfl_xor_sync(0xffffffffu, s, o);
    if (lane == 0) {
        s += attb[0];
        s = (s > 0.f) ? s : 0.01f * s;
        if (!node_mask[(size_t)b*Nn + n]) s = -1e9f;
        g_scores[gw] = s;
    }
}

// ---------------- softmax + top-20 + output (1 block / batch) ----------------
__global__ void __launch_bounds__(1024)
topk_kernel(const int* __restrict__ node_mask, float* __restrict__ out)
{
    __shared__ float ss[Nn];
    __shared__ float rv[1024];
    __shared__ int   ri[1024];
    __shared__ float s_max, s_sum;
    __shared__ int   top_i[Mm];
    __shared__ float top_v[Mm];

    int b = blockIdx.x;
    int t = threadIdx.x;

    for (int i = t; i < Nn; i += 1024) ss[i] = g_scores[(size_t)b*Nn + i];
    __syncthreads();

    float m = -INFINITY;
    for (int i = t; i < Nn; i += 1024) m = fmaxf(m, ss[i]);
    rv[t] = m; __syncthreads();
    for (int s = 512; s > 0; s >>= 1) { if (t < s) rv[t] = fmaxf(rv[t], rv[t+s]); __syncthreads(); }
    if (t == 0) s_max = rv[0];
    __syncthreads();
    float vmax = s_max;

    float sum = 0.f;
    for (int i = t; i < Nn; i += 1024) sum += expf(ss[i] - vmax);
    rv[t] = sum; __syncthreads();
    for (int s = 512; s > 0; s >>= 1) { if (t < s) rv[t] += rv[t+s]; __syncthreads(); }
    if (t == 0) s_sum = rv[0];
    __syncthreads();
    float inv = 1.f / s_sum;

    for (int sel = 0; sel < Mm; sel++) {
        float bv = -INFINITY; int bi = Nn;
        for (int i = t; i < Nn; i += 1024) {
            float v = ss[i];
            if (v > bv) { bv = v; bi = i; }
        }
        rv[t] = bv; ri[t] = bi; __syncthreads();
        for (int s = 512; s > 0; s >>= 1) {
            if (t < s) {
                if (rv[t+s] > rv[t] || (rv[t+s] == rv[t] && ri[t+s] < ri[t])) {
                    rv[t] = rv[t+s]; ri[t] = ri[t+s];
                }
            }
            __syncthreads();
        }
        if (t == 0) { top_i[sel] = ri[0]; top_v[sel] = rv[0]; ss[ri[0]] = -INFINITY; }
        __syncthreads();
    }

    for (int i = t; i < Mm*Dd; i += 1024) {
        int sel = i / Dd, d = i % Dd;
        int idx = top_i[sel];
        float alpha = expf(top_v[sel] - vmax) * inv;
        float mk = node_mask[(size_t)b*Nn + idx] ? 1.f : 0.f;
        float hv = g_h[((size_t)b*Nn + idx)*Dd + d] * mk;
        out[((size_t)b*Mm + sel)*Dd + d] = hv * alpha;
    }
    float m0 = node_mask[(size_t)b*Nn] ? 1.f : 0.f;
    for (int d = t; d < Dd; d += 1024)
        out[(size_t)Bk*Mm*Dd + (size_t)b*Dd + d] = g_h[((size_t)b*Nn)*Dd + d] * m0;
}

// ---------------- launch ----------------
extern "C" void kernel_launch(void* const* d_in, const int* in_sizes, int n_in,
                              void* d_out, int out_size)
{
    (void)in_sizes; (void)n_in; (void)out_size;
    const int*   dists      = (const int*)d_in[0];
    const int*   edge_index = (const int*)d_in[1];
    const int*   rels       = (const int*)d_in[2];
    const int*   node_mask  = (const int*)d_in[3];
    const int*   edge_mask  = (const int*)d_in[4];
    const float* rq         = (const float*)d_in[5];
    const float* conf       = (const float*)d_in[6];
    const float* noise      = (const float*)d_in[7];
    const float* dist_table = (const float*)d_in[8];
    const float* rel_table  = (const float*)d_in[9];
    const float* msg_W      = (const float*)d_in[10];
    const float* msg_b      = (const float*)d_in[11];
    const float* upd_W      = (const float*)d_in[12];
    const float* upd_b      = (const float*)d_in[13];
    const float* att_W      = (const float*)d_in[14];
    const float* att_b      = (const float*)d_in[15];
    float* out = (float*)d_out;

    cudaFuncSetAttribute(edge_hmma_kernel, cudaFuncAttributeMaxDynamicSharedMemorySize, (int)SM_BYTES);
    cudaFuncSetAttribute(update_hmma_kernel, cudaFuncAttributeMaxDynamicSharedMemorySize, (int)SM_BYTES);
    void* aggr_ptr = nullptr;
    cudaGetSymbolAddress(&aggr_ptr, g_aggr);

    int total4 = Bk*Nn*Dd/4;
    prep_kernel<<<(total4 + 255)/256, 256>>>(dists, noise, dist_table);
    prep_weights<<<(Ll*5*Dd*Dd + Ll*Dd*Dd + 255)/256, 256>>>(msg_W, upd_W);

    for (int l = 0; l < Ll; l++) {
        cudaMemsetAsync(aggr_ptr, 0, sizeof(float)*(size_t)Bk*Nn*Dd);
        edge_hmma_kernel<<<Bk*(Ee/128), 256, SM_BYTES>>>(
            l, edge_index, rels, edge_mask, conf, rel_table, msg_b + (size_t)l*Dd);
        update_hmma_kernel<<<Bk*Nn/128, 256, SM_BYTES>>>(l, upd_b + (size_t)l*Dd);
    }

    score_kernel<<<Bk*Nn/8, 256>>>(att_W, att_b, node_mask, rq);
    topk_kernel<<<Bk, 1024>>>(node_mask, out);
}

// round 6
// speedup vs baseline: 3.1035x; 1.0229x over previous
#include <cuda_runtime.h>
#include <cuda_fp16.h>
#include <math.h>
#include <stdint.h>

#define Bk 8
#define Nn 8192
#define Ee 16384
#define Dd 128
#define Mm 20
#define Ll 3
#define Rr 200

// ---- edge kernel geometry ----
#define CH 32                    // k-chunk
#define ESTR 40                  // smem row stride (halves): 80B = 5x16B, ldsm conflict-free
#define TILE_H (128*ESTR)        // 5120 halves per tile
#define STAGE_H (4*TILE_H)       // AHI, ALO, BHI, BLO
#define ESMEM (2*STAGE_H*2)      // 81920 bytes

// ---- update kernel geometry (R5, validated) ----
#define USTR 72
#define USMEM ((size_t)(4*128*USTR)*2)   // 73728

// -------- device scratch --------
__device__ float g_h[(size_t)Bk*Nn*Dd];
__device__ float g_de[(size_t)Bk*Nn*Dd];
__device__ float g_aggr[(size_t)Bk*Nn*Dd];
__device__ float g_scores[Bk*Nn];
__device__ __half g_hhi[(size_t)Bk*Nn*Dd],  g_hlo[(size_t)Bk*Nn*Dd];
__device__ __half g_dehi[(size_t)Bk*Nn*Dd], g_delo[(size_t)Bk*Nn*Dd];
__device__ __half g_confhi[(size_t)Bk*Ee*Dd], g_conflo[(size_t)Bk*Ee*Dd];
__device__ __half g_relhi[Rr*Dd], g_rello[Rr*Dd];
__device__ __half g_msgWhi[(size_t)Ll*20*128*32], g_msgWlo[(size_t)Ll*20*128*32];
__device__ __half g_updWhi[(size_t)Ll*2*128*64],  g_updWlo[(size_t)Ll*2*128*64];

__device__ __forceinline__ uint32_t smem_u32(const void* p){
    uint32_t a;
    asm("{ .reg .u64 t; cvta.to.shared.u64 t, %1; cvt.u32.u64 %0, t; }" : "=r"(a) : "l"(p));
    return a;
}
__device__ __forceinline__ void cpa16(uint32_t dst, const void* src){
    asm volatile("cp.async.cg.shared.global [%0], [%1], 16;" :: "r"(dst), "l"(src));
}
#define CP_COMMIT() asm volatile("cp.async.commit_group;" ::: "memory")

#define LDSM4(r, addr) \
    asm volatile("ldmatrix.sync.aligned.m8n8.x4.shared.b16 {%0,%1,%2,%3}, [%4];" \
        : "=r"((r)[0]), "=r"((r)[1]), "=r"((r)[2]), "=r"((r)[3]) : "r"(addr))

#define MMA_F16(c, a, b0, b1) \
    asm volatile("mma.sync.aligned.m16n8k16.row.col.f32.f16.f16.f32 " \
        "{%0,%1,%2,%3}, {%4,%5,%6,%7}, {%8,%9}, {%0,%1,%2,%3};" \
        : "+f"((c)[0]), "+f"((c)[1]), "+f"((c)[2]), "+f"((c)[3]) \
        : "r"((a)[0]), "r"((a)[1]), "r"((a)[2]), "r"((a)[3]), "r"(b0), "r"(b1))

// ---------------- prep: dist_emb + h init (+ fp16 splits) ----------------
__global__ void prep_kernel(const int* __restrict__ dists,
                            const float* __restrict__ noise,
                            const float* __restrict__ dtab)
{
    int i = blockIdx.x * blockDim.x + threadIdx.x;
    if (i >= Bk*Nn*Dd/4) return;
    int node = i >> 5;
    int c = i & 31;
    int di = dists[node];
    di = di < 0 ? 0 : (di > 9 ? 9 : di);
    float4 dv = __ldg(((const float4*)(dtab + (size_t)di*Dd)) + c);
    float4 nz = ((const float4*)noise)[i];
    float4 h;
    h.x = dv.x + 0.1f*nz.x; h.y = dv.y + 0.1f*nz.y;
    h.z = dv.z + 0.1f*nz.z; h.w = dv.w + 0.1f*nz.w;
    ((float4*)g_de)[i] = dv;
    ((float4*)g_h)[i]  = h;

    __half2* p;
    __half a0, a1;
    // h split
    a0 = __float2half_rn(h.x); a1 = __float2half_rn(h.y);
    p = (__half2*)g_hhi; p[2*i] = __halves2half2(a0, a1);
    p = (__half2*)g_hlo; p[2*i] = __halves2half2(__float2half_rn(h.x-__half2float(a0)), __float2half_rn(h.y-__half2float(a1)));
    a0 = __float2half_rn(h.z); a1 = __float2half_rn(h.w);
    p = (__half2*)g_hhi; p[2*i+1] = __halves2half2(a0, a1);
    p = (__half2*)g_hlo; p[2*i+1] = __halves2half2(__float2half_rn(h.z-__half2float(a0)), __float2half_rn(h.w-__half2float(a1)));
    // de split
    a0 = __float2half_rn(dv.x); a1 = __float2half_rn(dv.y);
    p = (__half2*)g_dehi; p[2*i] = __halves2half2(a0, a1);
    p = (__half2*)g_delo; p[2*i] = __halves2half2(__float2half_rn(dv.x-__half2float(a0)), __float2half_rn(dv.y-__half2float(a1)));
    a0 = __float2half_rn(dv.z); a1 = __float2half_rn(dv.w);
    p = (__half2*)g_dehi; p[2*i+1] = __halves2half2(a0, a1);
    p = (__half2*)g_delo; p[2*i+1] = __halves2half2(__float2half_rn(dv.z-__half2float(a0)), __float2half_rn(dv.w-__half2float(a1)));
}

// ---------------- prep: conf + rel_table fp16 splits ----------------
__global__ void prep_aux(const float* __restrict__ conf, const float* __restrict__ rel_table)
{
    int i = blockIdx.x * blockDim.x + threadIdx.x;
    const int CT = Bk*Ee*Dd/4;
    float4 v; __half* hi; __half* lo; int base;
    if (i < CT) { v = ((const float4*)conf)[i]; hi = g_confhi; lo = g_conflo; base = i*4; }
    else {
        int j = i - CT;
        if (j >= Rr*Dd/4) return;
        v = ((const float4*)rel_table)[j]; hi = g_relhi; lo = g_rello; base = j*4;
    }
    __half a0 = __float2half_rn(v.x), a1 = __float2half_rn(v.y);
    __half a2 = __float2half_rn(v.z), a3 = __float2half_rn(v.w);
    *(__half2*)(hi + base)     = __halves2half2(a0, a1);
    *(__half2*)(hi + base + 2) = __halves2half2(a2, a3);
    *(__half2*)(lo + base)     = __halves2half2(__float2half_rn(v.x-__half2float(a0)), __float2half_rn(v.y-__half2float(a1)));
    *(__half2*)(lo + base + 2) = __halves2half2(__float2half_rn(v.z-__half2float(a2)), __float2half_rn(v.w-__half2float(a3)));
}

// ---------------- weight prep ----------------
__global__ void prep_weights(const float* __restrict__ msgW, const float* __restrict__ updW)
{
    int i = blockIdx.x * blockDim.x + threadIdx.x;
    const int MSGTOT = Ll*5*Dd*Dd;
    if (i < MSGTOT) {
        int l = i / (640*128);
        int k = (i / 128) % 640;
        int n = i & 127;
        int ch = k >> 5, kk = k & 31;       // k32 chunks for edge kernel
        float w = msgW[i];
        __half hi = __float2half_rn(w);
        __half lo = __float2half_rn(w - __half2float(hi));
        size_t o = (((size_t)(l*20 + ch))*128 + n)*32 + kk;
        g_msgWhi[o] = hi; g_msgWlo[o] = lo;
    } else {
        int j = i - MSGTOT;
        if (j < Ll*Dd*Dd) {
            int l = j / (128*128);
            int k = (j / 128) % 128;
            int n = j & 127;
            int ch = k >> 6, kk = k & 63;   // k64 chunks for update kernel
            float w = updW[j];
            __half hi = __float2half_rn(w);
            __half lo = __float2half_rn(w - __half2float(hi));
            size_t o = (((size_t)(l*2 + ch))*128 + n)*64 + kk;
            g_updWhi[o] = hi; g_updWlo[o] = lo;
        }
    }
}

// ---------------- edge message GEMM: cp.async pipeline + ldmatrix + fp16-split MMA ----------------
// CTA: 128 edges x 128 out, K=640 as 20 k32-chunks. 8 warps 4(M)x2(N), warp tile 32x64.
// chunk 0-15: segs h,de,rel,conf (pure 16B copies, pre-split). chunk 16-19: comp (computed fill).
__global__ void __launch_bounds__(256, 2)
edge_hmma_kernel(int layer,
                 const int* __restrict__ edge_index,
                 const int* __restrict__ rels,
                 const int* __restrict__ edge_mask,
                 const float* __restrict__ rel_table,
                 const float* __restrict__ bias)
{
    extern __shared__ __half sm[];
    __shared__ int   s_src[128], s_tgt[128], s_rel[128];
    __shared__ float s_em[128], s_bias[128];

    int tid = threadIdx.x, wid = tid >> 5, lane = tid & 31;
    int b  = blockIdx.x >> 7;
    int e0 = (blockIdx.x & 127) << 7;

    if (tid < 128) {
        int e = e0 + tid;
        s_src[tid] = edge_index[(size_t)b*2*Ee + e];
        s_tgt[tid] = edge_index[(size_t)b*2*Ee + Ee + e];
        s_rel[tid] = rels[(size_t)b*Ee + e];
        s_em[tid]  = edge_mask[(size_t)b*Ee + e] ? 1.f : 0.f;
        s_bias[tid] = bias[tid];
    }
    __syncthreads();

    uint32_t smb = smem_u32(sm);
    size_t bN = (size_t)b * Nn;
    int wm = wid & 3, wn = wid >> 2;
    int g = lane >> 2, t4 = lane & 3;

    float acc[2][8][4];
    #pragma unroll
    for (int i = 0; i < 2; i++)
        #pragma unroll
        for (int j = 0; j < 8; j++)
            #pragma unroll
            for (int q = 0; q < 4; q++) acc[i][j][q] = 0.f;

    // async copy issue for chunk c into stage st (B always; A only for c<16)
    auto issue = [&](int c, int st){
        uint32_t sb = smb + (uint32_t)(st*STAGE_H)*2;
        int wc = (c < 16) ? c + 4 : c - 16;
        const __half* wh = g_msgWhi + ((size_t)(layer*20 + wc))*4096;
        const __half* wl = g_msgWlo + ((size_t)(layer*20 + wc))*4096;
        #pragma unroll
        for (int r = 0; r < 2; r++){
            int idx = tid + r*256;
            int n = idx >> 2, f = idx & 3;
            uint32_t d = sb + (uint32_t)(2*TILE_H + n*ESTR + f*8)*2;
            cpa16(d,              wh + n*32 + f*8);
            cpa16(d + TILE_H*2,   wl + n*32 + f*8);
        }
        if (c < 16){
            int sg = c >> 2;
            int koff = (c & 3)*CH;
            #pragma unroll
            for (int r = 0; r < 2; r++){
                int idx = tid + r*256;
                int e = idx >> 2, q = idx & 3;
                size_t rowoff;
                const __half *ph, *pl;
                if (sg == 0)      { rowoff = (bN + s_src[e])*Dd; ph = g_hhi;   pl = g_hlo; }
                else if (sg == 1) { rowoff = (bN + s_src[e])*Dd; ph = g_dehi;  pl = g_delo; }
                else if (sg == 2) { rowoff = (size_t)s_rel[e]*Dd; ph = g_relhi; pl = g_rello; }
                else              { rowoff = ((size_t)b*Ee + e0 + e)*Dd; ph = g_confhi; pl = g_conflo; }
                uint32_t d = sb + (uint32_t)(e*ESTR + q*8)*2;
                cpa16(d,            ph + rowoff + koff + q*8);
                cpa16(d + TILE_H*2, pl + rowoff + koff + q*8);
            }
        }
    };
    // computed fill for comp chunks (16..19)
    auto fill0 = [&](int c, int st){
        __half* base = sm + st*STAGE_H;
        int koff = (c - 16)*CH;
        #pragma unroll
        for (int r = 0; r < 2; r++){
            int idx = tid + r*256;
            int e = idx >> 2, q = idx & 3;
            const float* hp = g_h + (bN + s_src[e])*Dd + koff + q*8;
            const float* rp = rel_table + (size_t)s_rel[e]*Dd + koff + q*8;
            float4 h1 = *(const float4*)hp, h2 = *(const float4*)(hp + 4);
            float4 r1 = *(const float4*)rp, r2 = *(const float4*)(rp + 4);
            float pr[8] = {h1.x*r1.x, h1.y*r1.y, h1.z*r1.z, h1.w*r1.w,
                           h2.x*r2.x, h2.y*r2.y, h2.z*r2.z, h2.w*r2.w};
            __half hh[8], ll[8];
            #pragma unroll
            for (int u = 0; u < 8; u++){
                hh[u] = __float2half_rn(pr[u]);
                ll[u] = __float2half_rn(pr[u] - __half2float(hh[u]));
            }
            *(uint4*)(base + e*ESTR + q*8)          = *(uint4*)hh;
            *(uint4*)(base + TILE_H + e*ESTR + q*8) = *(uint4*)ll;
        }
    };

    issue(0, 0); CP_COMMIT();

    for (int c = 0; c < 20; c++){
        int st = c & 1, nst = st ^ 1;
        if (c + 1 < 20){
            issue(c + 1, nst);
            if (c + 1 >= 16) fill0(c + 1, nst);
            CP_COMMIT();
            asm volatile("cp.async.wait_group 1;" ::: "memory");
        } else {
            asm volatile("cp.async.wait_group 0;" ::: "memory");
        }
        __syncthreads();

        uint32_t sb = smb + (uint32_t)(st*STAGE_H)*2;
        #pragma unroll
        for (int k16 = 0; k16 < 2; k16++){
            int kb = k16*16;
            uint32_t ah[2][4], al[2][4];
            #pragma unroll
            for (int i = 0; i < 2; i++){
                uint32_t a = sb + (uint32_t)((wm*32 + i*16 + (lane & 15))*ESTR + kb + (lane >> 4)*8)*2;
                LDSM4(ah[i], a);
                LDSM4(al[i], a + TILE_H*2);
            }
            #pragma unroll
            for (int jp = 0; jp < 4; jp++){
                uint32_t bb = sb + (uint32_t)(2*TILE_H + (wn*64 + jp*16 + (lane & 15))*ESTR + kb + (lane >> 4)*8)*2;
                uint32_t bh[4], bl[4];
                LDSM4(bh, bb);
                LDSM4(bl, bb + TILE_H*2);
                #pragma unroll
                for (int i = 0; i < 2; i++){
                    MMA_F16(acc[i][jp*2+0], ah[i], bh[0], bh[2]);
                    MMA_F16(acc[i][jp*2+1], ah[i], bh[1], bh[3]);
                    MMA_F16(acc[i][jp*2+0], ah[i], bl[0], bl[2]);
                    MMA_F16(acc[i][jp*2+1], ah[i], bl[1], bl[3]);
                    MMA_F16(acc[i][jp*2+0], al[i], bh[0], bh[2]);
                    MMA_F16(acc[i][jp*2+1], al[i], bh[1], bh[3]);
                }
            }
        }
        __syncthreads();
    }

    // epilogue: relu + bias + mask, scatter-add (validated R5 mapping)
    #pragma unroll
    for (int i = 0; i < 2; i++) {
        #pragma unroll
        for (int half = 0; half < 2; half++) {
            int row = wm*32 + i*16 + g + half*8;
            if (s_em[row] != 0.f) {
                float* dst = g_aggr + (bN + s_tgt[row])*Dd;
                #pragma unroll
                for (int j = 0; j < 8; j++) {
                    int col = wn*64 + j*8 + t4*2;
                    float v0 = acc[i][j][half*2+0] + s_bias[col];
                    float v1 = acc[i][j][half*2+1] + s_bias[col+1];
                    if (v0 > 0.f) atomicAdd(dst + col,     v0);
                    if (v1 > 0.f) atomicAdd(dst + col + 1, v1);
                }
            }
        }
    }
}

// ---------------- node update GEMM (R5, validated) + fused h re-split ----------------
__global__ void __launch_bounds__(256, 2)
update_hmma_kernel(int layer, const float* __restrict__ bias)
{
    extern __shared__ __half sm[];
    __half* sAhi = sm;
    __half* sAlo = sAhi + 128*USTR;
    __half* sBhi = sAlo + 128*USTR;
    __half* sBlo = sBhi + 128*USTR;
    __shared__ float s_bias[128];

    int tid = threadIdx.x, wid = tid >> 5, lane = tid & 31;
    size_t r0 = (size_t)blockIdx.x * 128;
    if (tid < 128) s_bias[tid] = bias[tid];
    __syncthreads();

    int wm = wid & 3, wn = wid >> 2;
    int g = lane >> 2, t4 = lane & 3;

    float acc[2][8][4];
    #pragma unroll
    for (int i = 0; i < 2; i++)
        #pragma unroll
        for (int j = 0; j < 8; j++)
            #pragma unroll
            for (int q = 0; q < 4; q++) acc[i][j][q] = 0.f;

    for (int c = 0; c < 2; c++) {
        int koff = c*64;
        #pragma unroll
        for (int it = 0; it < 8; it++) {
            int idx = tid + it*256;
            int row = idx >> 4, q = idx & 15;
            float4 v = *(const float4*)(g_aggr + (r0 + row)*Dd + koff + q*4);
            __half h0 = __float2half_rn(v.x), h1 = __float2half_rn(v.y);
            __half h2 = __float2half_rn(v.z), h3 = __float2half_rn(v.w);
            __half2 hiA = __halves2half2(h0, h1), hiB = __halves2half2(h2, h3);
            __half2 loA = __halves2half2(__float2half_rn(v.x-__half2float(h0)), __float2half_rn(v.y-__half2float(h1)));
            __half2 loB = __halves2half2(__float2half_rn(v.z-__half2float(h2)), __float2half_rn(v.w-__half2float(h3)));
            int ho = row*USTR + q*4;
            *(__half2*)(sAhi + ho)     = hiA;
            *(__half2*)(sAhi + ho + 2) = hiB;
            *(__half2*)(sAlo + ho)     = loA;
            *(__half2*)(sAlo + ho + 2) = loB;
        }
        {
            const uint4* wh = (const uint4*)(g_updWhi + ((size_t)(layer*2 + c))*8192);
            const uint4* wl = (const uint4*)(g_updWlo + ((size_t)(layer*2 + c))*8192);
            #pragma unroll
            for (int it = 0; it < 4; it++) {
                int idx = tid + it*256;
                int n = idx >> 3, q = idx & 7;
                *(uint4*)(sBhi + n*USTR + q*8) = __ldg(wh + idx);
                *(uint4*)(sBlo + n*USTR + q*8) = __ldg(wl + idx);
            }
        }
        __syncthreads();

        #pragma unroll
        for (int k16 = 0; k16 < 4; k16++) {
            int kb = k16*16;
            uint32_t ahi[2][4], alo[2][4];
            #pragma unroll
            for (int i = 0; i < 2; i++) {
                uint32_t a = smem_u32(sAhi + (wm*32 + i*16 + (lane & 15))*USTR + kb + (lane >> 4)*8);
                LDSM4(ahi[i], a);
                LDSM4(alo[i], a + 128*USTR*2);
            }
            #pragma unroll
            for (int jp = 0; jp < 4; jp++) {
                uint32_t bb = smem_u32(sBhi + (wn*64 + jp*16 + (lane & 15))*USTR + kb + (lane >> 4)*8);
                uint32_t bh[4], bl[4];
                LDSM4(bh, bb);
                LDSM4(bl, bb + 128*USTR*2);
                #pragma unroll
                for (int i = 0; i < 2; i++) {
                    MMA_F16(acc[i][jp*2+0], ahi[i], bh[0], bh[2]);
                    MMA_F16(acc[i][jp*2+1], ahi[i], bh[1], bh[3]);
                    MMA_F16(acc[i][jp*2+0], ahi[i], bl[0], bl[2]);
                    MMA_F16(acc[i][jp*2+1], ahi[i], bl[1], bl[3]);
                    MMA_F16(acc[i][jp*2+0], alo[i], bh[0], bh[2]);
                    MMA_F16(acc[i][jp*2+1], alo[i], bh[1], bh[3]);
                }
            }
        }
        __syncthreads();
    }

    // epilogue: h += d + bias; also write fp16 hi/lo split of new h
    #pragma unroll
    for (int i = 0; i < 2; i++) {
        #pragma unroll
        for (int half = 0; half < 2; half++) {
            int row = wm*32 + i*16 + g + half*8;
            size_t gro = (r0 + row)*Dd;
            float* hp = g_h + gro;
            #pragma unroll
            for (int j = 0; j < 8; j++) {
                int col = wn*64 + j*8 + t4*2;
                float v0 = hp[col]     + acc[i][j][half*2+0] + s_bias[col];
                float v1 = hp[col + 1] + acc[i][j][half*2+1] + s_bias[col+1];
                hp[col] = v0; hp[col + 1] = v1;
                __half a0 = __float2half_rn(v0), a1 = __float2half_rn(v1);
                *(__half2*)(g_hhi + gro + col) = __halves2half2(a0, a1);
                *(__half2*)(g_hlo + gro + col) = __halves2half2(
                    __float2half_rn(v0 - __half2float(a0)),
                    __float2half_rn(v1 - __half2float(a1)));
            }
        }
    }
}

// ---------------- attention scores ----------------
__global__ void score_kernel(const float* __restrict__ attW, const float* __restrict__ attb,
                             const int* __restrict__ node_mask,
                             const float* __restrict__ rq)
{
    int gw = blockIdx.x*8 + (threadIdx.x >> 5);
    int lane = threadIdx.x & 31;
    int b = gw / Nn, n = gw % Nn;
    const float* hrow = g_h + (size_t)gw*Dd;
    float s = 0.f;
    #pragma unroll
    for (int i = 0; i < 4; i++) {
        int d = lane + i*32;
        s = fmaf(hrow[d], attW[d], s);
        s = fmaf(rq[b*Dd + d], attW[Dd + d], s);
    }
    #pragma unroll
    for (int o = 16; o; o >>= 1) s += __shfl_xor_sync(0xffffffffu, s, o);
    if (lane == 0) {
        s += attb[0];
        s = (s > 0.f) ? s : 0.01f * s;
        if (!node_mask[(size_t)b*Nn + n]) s = -1e9f;
        g_scores[gw] = s;
    }
}

// ---------------- softmax + top-20 + output (1 block / batch) ----------------
__global__ void __launch_bounds__(1024)
topk_kernel(const int* __restrict__ node_mask, float* __restrict__ out)
{
    __shared__ float ss[Nn];
    __shared__ float rv[1024];
    __shared__ int   ri[1024];
    __shared__ float s_max, s_sum;
    __shared__ int   top_i[Mm];
    __shared__ float top_v[Mm];

    int b = blockIdx.x;
    int t = threadIdx.x;

    for (int i = t; i < Nn; i += 1024) ss[i] = g_scores[(size_t)b*Nn + i];
    __syncthreads();

    float m = -INFINITY;
    for (int i = t; i < Nn; i += 1024) m = fmaxf(m, ss[i]);
    rv[t] = m; __syncthreads();
    for (int s = 512; s > 0; s >>= 1) { if (t < s) rv[t] = fmaxf(rv[t], rv[t+s]); __syncthreads(); }
    if (t == 0) s_max = rv[0];
    __syncthreads();
    float vmax = s_max;

    float sum = 0.f;
    for (int i = t; i < Nn; i += 1024) sum += expf(ss[i] - vmax);
    rv[t] = sum; __syncthreads();
    for (int s = 512; s > 0; s >>= 1) { if (t < s) rv[t] += rv[t+s]; __syncthreads(); }
    if (t == 0) s_sum = rv[0];
    __syncthreads();
    float inv = 1.f / s_sum;

    for (int sel = 0; sel < Mm; sel++) {
        float bv = -INFINITY; int bi = Nn;
        for (int i = t; i < Nn; i += 1024) {
            float v = ss[i];
            if (v > bv) { bv = v; bi = i; }
        }
        rv[t] = bv; ri[t] = bi; __syncthreads();
        for (int s = 512; s > 0; s >>= 1) {
            if (t < s) {
                if (rv[t+s] > rv[t] || (rv[t+s] == rv[t] && ri[t+s] < ri[t])) {
                    rv[t] = rv[t+s]; ri[t] = ri[t+s];
                }
            }
            __syncthreads();
        }
        if (t == 0) { top_i[sel] = ri[0]; top_v[sel] = rv[0]; ss[ri[0]] = -INFINITY; }
        __syncthreads();
    }

    for (int i = t; i < Mm*Dd; i += 1024) {
        int sel = i / Dd, d = i % Dd;
        int idx = top_i[sel];
        float alpha = expf(top_v[sel] - vmax) * inv;
        float mk = node_mask[(size_t)b*Nn + idx] ? 1.f : 0.f;
        float hv = g_h[((size_t)b*Nn + idx)*Dd + d] * mk;
        out[((size_t)b*Mm + sel)*Dd + d] = hv * alpha;
    }
    float m0 = node_mask[(size_t)b*Nn] ? 1.f : 0.f;
    for (int d = t; d < Dd; d += 1024)
        out[(size_t)Bk*Mm*Dd + (size_t)b*Dd + d] = g_h[((size_t)b*Nn)*Dd + d] * m0;
}

// ---------------- launch ----------------
extern "C" void kernel_launch(void* const* d_in, const int* in_sizes, int n_in,
                              void* d_out, int out_size)
{
    (void)in_sizes; (void)n_in; (void)out_size;
    const int*   dists      = (const int*)d_in[0];
    const int*   edge_index = (const int*)d_in[1];
    const int*   rels       = (const int*)d_in[2];
    const int*   node_mask  = (const int*)d_in[3];
    const int*   edge_mask  = (const int*)d_in[4];
    const float* rq         = (const float*)d_in[5];
    const float* conf       = (const float*)d_in[6];
    const float* noise      = (const float*)d_in[7];
    const float* dist_table = (const float*)d_in[8];
    const float* rel_table  = (const float*)d_in[9];
    const float* msg_W      = (const float*)d_in[10];
    const float* msg_b      = (const float*)d_in[11];
    const float* upd_W      = (const float*)d_in[12];
    const float* upd_b      = (const float*)d_in[13];
    const float* att_W      = (const float*)d_in[14];
    const float* att_b      = (const float*)d_in[15];
    float* out = (float*)d_out;

    cudaFuncSetAttribute(edge_hmma_kernel, cudaFuncAttributeMaxDynamicSharedMemorySize, ESMEM);
    cudaFuncSetAttribute(update_hmma_kernel, cudaFuncAttributeMaxDynamicSharedMemorySize, (int)USMEM);
    void* aggr_ptr = nullptr;
    cudaGetSymbolAddress(&aggr_ptr, g_aggr);

    int total4 = Bk*Nn*Dd/4;
    prep_kernel<<<(total4 + 255)/256, 256>>>(dists, noise, dist_table);
    prep_aux<<<(Bk*Ee*Dd/4 + Rr*Dd/4 + 255)/256, 256>>>(conf, rel_table);
    prep_weights<<<(Ll*5*Dd*Dd + Ll*Dd*Dd + 255)/256, 256>>>(msg_W, upd_W);

    for (int l = 0; l < Ll; l++) {
        cudaMemsetAsync(aggr_ptr, 0, sizeof(float)*(size_t)Bk*Nn*Dd);
        edge_hmma_kernel<<<Bk*(Ee/128), 256, ESMEM>>>(
            l, edge_index, rels, edge_mask, rel_table, msg_b + (size_t)l*Dd);
        update_hmma_kernel<<<Bk*Nn/128, 256, USMEM>>>(l, upd_b + (size_t)l*Dd);
    }

    score_kernel<<<Bk*Nn/8, 256>>>(att_W, att_b, node_mask, rq);
    topk_kernel<<<Bk, 1024>>>(node_mask, out);
}